// round 11
// baseline (speedup 1.0000x reference)
#include <cuda_runtime.h>
#include <cuda_fp16.h>

// Fixed problem shapes
#define TT 4
#define BB 512
#define GG 16
#define NN 256
#define DD 32
#define PADH 40                 // halves per smem row (80B): conflict-free .128 row access
#define GRID  BB                // one CTA per batch: full t-chain, max slice reuse
#define NEG_BIG_F (-1e30f)

__device__ double g_acc[5];        // zwl, zpl, pl(sum cos*w), ol, nobj
__device__ unsigned int g_count;   // zero-init; reset by last CTA each replay

__device__ __forceinline__ unsigned h2u(half2 h) { return *reinterpret_cast<unsigned*>(&h); }
__device__ __forceinline__ half2    u2h(unsigned u) { return *reinterpret_cast<half2*>(&u); }
__device__ __forceinline__ float    hsumf(half2 h) { float2 f = __half22float2(h); return f.x + f.y; }

__global__ __launch_bounds__(256, 5) void losses_kernel(
    const float* __restrict__ z_what,
    const float* __restrict__ z_pres_prob,
    const float* __restrict__ z_pres,
    const float* __restrict__ base_losses,
    const void*  __restrict__ step_ptr,
    float* __restrict__ out, int out_size)
{
    const int tid = threadIdx.x;
    const int n   = tid;               // one thread per grid cell
    const int i   = n >> 4, j = n & 15;
    const int bb  = blockIdx.x;        // batch owned by this CTA

    extern __shared__ char smraw[];
    half*  buf0 = (half*)smraw;                     // [NN][PADH] fp16 slice buffer
    half*  buf1 = buf0 + NN * PADH;                 // [NN][PADH] fp16 slice buffer
    float* s_pb = (float*)(smraw + (size_t)2 * NN * PADH * sizeof(half));
    float* s_nb = s_pb + NN;                        // 1 / ||wb[m]||
    float* s_red = s_nb + NN;                       // 40 floats

    float acc0 = 0.f, acc1 = 0.f, acc2 = 0.f, acc3 = 0.f, acc4 = 0.f;

    half* A = buf0;   // wa / hm buffer (destroyed by pool1 each pair)
    half* B = buf1;   // wb buffer (survives the pair)

    float pa_carry = z_pres_prob[(size_t)bb * NN + n];   // prob @ t=0
    float rp_carry = 0.f;                                 // 1/||wa|| carried from prev pair

    #pragma unroll 1
    for (int tt = 0; tt < TT - 1; ++tt) {
        const bool reuse = (tt > 0);

        const size_t slice = (size_t)NN * DD;
        const float4* ga4 = (const float4*)(z_what + ((size_t)tt * BB + bb) * slice);
        const float4* gb4 = (const float4*)((const float*)ga4 + (size_t)BB * slice);

        float zwl = 0.f;
        if (!reuse) {
            // ---- fresh: coalesced load of both slices; zwl exact fp32 ----
            #pragma unroll
            for (int it = 0; it < 8; ++it) {
                int k4 = it * 256 + tid;
                float4 va = ga4[k4];
                float4 vb = gb4[k4];
                int nn = k4 >> 3;
                int d0 = (k4 & 7) * 4;
                float dx = vb.x - va.x, dy = vb.y - va.y, dz = vb.z - va.z, dw = vb.w - va.w;
                zwl += dx*dx + dy*dy + dz*dz + dw*dw;
                half2 a0 = __floats2half2_rn(va.x, va.y), a1 = __floats2half2_rn(va.z, va.w);
                half2 b0 = __floats2half2_rn(vb.x, vb.y), b1 = __floats2half2_rn(vb.z, vb.w);
                *(uint2*)(A + nn * PADH + d0) = make_uint2(h2u(a0), h2u(a1));
                *(uint2*)(B + nn * PADH + d0) = make_uint2(h2u(b0), h2u(b1));
            }
        } else {
            // ---- reuse: previous wb becomes wa; load only new wb slice ----
            half* tmp = A; A = B; B = tmp;     // A = intact old wb; B = hm-trashed buffer
            #pragma unroll
            for (int it = 0; it < 8; ++it) {
                int k4 = it * 256 + tid;
                float4 vb = gb4[k4];
                int nn = k4 >> 3;
                int d0 = (k4 & 7) * 4;
                uint2 va16 = *(const uint2*)(A + nn * PADH + d0);
                float2 f01 = __half22float2(u2h(va16.x));
                float2 f23 = __half22float2(u2h(va16.y));
                float dx = vb.x - f01.x, dy = vb.y - f01.y;
                float dz = vb.z - f23.x, dw = vb.w - f23.y;
                zwl += dx*dx + dy*dy + dz*dz + dw*dw;
                half2 b0 = __floats2half2_rn(vb.x, vb.y), b1 = __floats2half2_rn(vb.z, vb.w);
                *(uint2*)(B + nn * PADH + d0) = make_uint2(h2u(b0), h2u(b1));
            }
        }
        acc0 += zwl;
        const float pa_n = pa_carry;
        const float pb_n = z_pres_prob[((size_t)(tt + 1) * BB + bb) * NN + n];
        pa_carry = pb_n;
        s_pb[n] = pb_n;

        // ---- z_pres loss (tt = 0,1 windows only) ----
        if (tt < TT - 2) {
            const float* zp = z_pres + ((size_t)tt * BB + bb) * NN + n;
            float p0 = zp[0];
            float p1 = zp[(size_t)BB * NN];
            float p2 = zp[2 * (size_t)BB * NN];
            float sim = 1.f - (p2 - p0) * (p2 - p0);
            float del = (p2 - p1) * (p2 - p1) + (p0 - p1) * (p0 - p1);
            acc1 += sim * del;
        }
        __syncthreads();

        // ---- own rows: pr2 regs; nb2/dotc (+pn2 only when fresh) ----
        half2 pr2[16];
        half2 pnA = __float2half2_rn(0.f), pnB = pnA;
        half2 nbA = pnA, nbB = pnA, dcA = pnA, dcB = pnA;
        {
            const uint4* ra = (const uint4*)(A + n * PADH);
            const uint4* rb = (const uint4*)(B + n * PADH);
            #pragma unroll
            for (int k = 0; k < 4; ++k) {
                uint4 qa = ra[k], qb = rb[k];
                half2 a0 = u2h(qa.x), a1 = u2h(qa.y), a2 = u2h(qa.z), a3 = u2h(qa.w);
                half2 b0 = u2h(qb.x), b1 = u2h(qb.y), b2 = u2h(qb.z), b3 = u2h(qb.w);
                pr2[4*k+0] = a0; pr2[4*k+1] = a1; pr2[4*k+2] = a2; pr2[4*k+3] = a3;
                nbA = __hfma2(b0, b0, nbA); nbB = __hfma2(b1, b1, nbB);
                nbA = __hfma2(b2, b2, nbA); nbB = __hfma2(b3, b3, nbB);
                dcA = __hfma2(a0, b0, dcA); dcB = __hfma2(a1, b1, dcB);
                dcA = __hfma2(a2, b2, dcA); dcB = __hfma2(a3, b3, dcB);
                if (!reuse) {
                    pnA = __hfma2(a0, a0, pnA); pnB = __hfma2(a1, a1, pnB);
                    pnA = __hfma2(a2, a2, pnA); pnB = __hfma2(a3, a3, pnB);
                }
            }
        }
        const float nbn  = sqrtf(hsumf(__hadd2(nbA, nbB)));
        const float dotc = hsumf(__hadd2(dcA, dcB));
        const float rnb  = __fdividef(1.f, fmaxf(nbn, 1e-20f));
        s_nb[n] = rnb;
        // 1/prior_n: fresh -> compute; reuse -> carried 1/||old wb|| (same fp16 data)
        const float rp = reuse ? rp_carry
                               : __fdividef(1.f, fmaxf(sqrtf(hsumf(__hadd2(pnA, pnB))), 1e-20f));
        rp_carry = rnb;

        // ---- pool pass 1: horizontal 3-max of |pr|*pa, own-row overwrite (safe) ----
        {
            const half2 pa2 = __float2half2_rn(pa_n);
            const bool lok = (j > 0), rok = (j < 15);
            uint4* rowh = (uint4*)(A + n * PADH);
            #pragma unroll
            for (int k4o = 0; k4o < 4; ++k4o) {
                unsigned hv[4];
                #pragma unroll
                for (int c = 0; c < 4; ++c) {
                    half2 wv = __hmul2(__habs2(pr2[4 * k4o + c]), pa2);
                    unsigned w = h2u(wv);
                    unsigned l = __shfl_up_sync(0xffffffffu, w, 1);
                    unsigned r = __shfl_down_sync(0xffffffffu, w, 1);
                    half2 hm = wv;
                    if (lok) hm = __hmax2(hm, u2h(l));
                    if (rok) hm = __hmax2(hm, u2h(r));
                    hv[c] = h2u(hm);
                }
                rowh[k4o] = make_uint4(hv[0], hv[1], hv[2], hv[3]);
            }
        }
        __syncthreads();

        // ---- pool pass 2: vertical 3-max + cosine (split accumulators) ----
        half2 dpA = __float2half2_rn(0.f), dpB = dpA, naA = dpA, naB = dpA;
        {
            const uint4* r0 = (const uint4*)(A + n * PADH);
            const uint4* ru = (i > 0)  ? (const uint4*)(A + (n - 16) * PADH) : r0;
            const uint4* rd = (i < 15) ? (const uint4*)(A + (n + 16) * PADH) : r0;
            const uint4* rb = (const uint4*)(B + n * PADH);
            #pragma unroll
            for (int k = 0; k < 4; ++k) {
                uint4 q0 = r0[k], qu = ru[k], qd = rd[k], qb = rb[k];
                half2 m0 = __hmax2(u2h(q0.x), __hmax2(u2h(qu.x), u2h(qd.x)));
                half2 m1 = __hmax2(u2h(q0.y), __hmax2(u2h(qu.y), u2h(qd.y)));
                half2 m2 = __hmax2(u2h(q0.z), __hmax2(u2h(qu.z), u2h(qd.z)));
                half2 m3 = __hmax2(u2h(q0.w), __hmax2(u2h(qu.w), u2h(qd.w)));
                dpA = __hfma2(m0, __habs2(u2h(qb.x)), dpA);
                dpB = __hfma2(m1, __habs2(u2h(qb.y)), dpB);
                dpA = __hfma2(m2, __habs2(u2h(qb.z)), dpA);
                dpB = __hfma2(m3, __habs2(u2h(qb.w)), dpB);
                naA = __hfma2(m0, m0, naA); naB = __hfma2(m1, m1, naB);
                naA = __hfma2(m2, m2, naA); naB = __hfma2(m3, m3, naB);
            }
        }
        {
            float dotp = hsumf(__hadd2(dpA, dpB));
            float na2  = hsumf(__hadd2(naA, naB));
            float cosim = __fdividef(dotp * pb_n, fmaxf(sqrtf(na2) * (pb_n * nbn), 1e-6f));
            acc2 += cosim * 0.5f * (pa_n + pb_n);  // pool_loss = -sum
        }

        // ---- objects: 8 branchless neighbor dots, 4-way trees, no divisions ----
        float sumd, maxd;
        bool anyp;
        {
            bool pc = pb_n > 0.5f;
            float vc = dotc * rp * rnb;
            sumd = pc ? vc : 0.f;
            maxd = pc ? vc : NEG_BIG_F;
            anyp = pc;
        }
        const int DI[8] = {-1,-1,-1, 0, 0, 1, 1, 1};
        const int DJ[8] = {-1, 0, 1,-1, 1,-1, 0, 1};
        #pragma unroll
        for (int q = 0; q < 8; ++q) {
            const int m = (((i + DI[q]) & 15) << 4) | ((j + DJ[q]) & 15);
            const float pbm = s_pb[m];
            const float rnm = s_nb[m];
            const uint4* rn4 = (const uint4*)(B + m * PADH);
            uint4 q0 = rn4[0], q1 = rn4[1], q2 = rn4[2], q3 = rn4[3];
            half2 d0 = __hmul2(pr2[0],  u2h(q0.x));
            half2 d1 = __hmul2(pr2[1],  u2h(q0.y));
            half2 d2 = __hmul2(pr2[2],  u2h(q0.z));
            half2 d3 = __hmul2(pr2[3],  u2h(q0.w));
            d0 = __hfma2(pr2[4],  u2h(q1.x), d0);
            d1 = __hfma2(pr2[5],  u2h(q1.y), d1);
            d2 = __hfma2(pr2[6],  u2h(q1.z), d2);
            d3 = __hfma2(pr2[7],  u2h(q1.w), d3);
            d0 = __hfma2(pr2[8],  u2h(q2.x), d0);
            d1 = __hfma2(pr2[9],  u2h(q2.y), d1);
            d2 = __hfma2(pr2[10], u2h(q2.z), d2);
            d3 = __hfma2(pr2[11], u2h(q2.w), d3);
            d0 = __hfma2(pr2[12], u2h(q3.x), d0);
            d1 = __hfma2(pr2[13], u2h(q3.y), d1);
            d2 = __hfma2(pr2[14], u2h(q3.z), d2);
            d3 = __hfma2(pr2[15], u2h(q3.w), d3);
            half2 ds = __hadd2(__hadd2(d0, d1), __hadd2(d2, d3));
            float v = hsumf(ds) * rp * rnm;
            bool pq = pbm > 0.5f;
            sumd += pq ? v : 0.f;
            maxd = fmaxf(maxd, pq ? v : NEG_BIG_F);
            anyp |= pq;
        }
        {
            bool detected = pa_n > 0.5f;
            if (detected && anyp) acc3 += sumd - 5.f * maxd;
            if (detected) acc4 += 1.f;
        }

        __syncthreads();   // protect smem before next iteration's staging
    }

    // ---- one block reduction per CTA + global accumulate ----
    float vals[5] = {acc0, acc1, acc2, acc3, acc4};
    #pragma unroll
    for (int k = 0; k < 5; ++k) {
        float v = vals[k];
        #pragma unroll
        for (int o = 16; o > 0; o >>= 1) v += __shfl_down_sync(0xffffffffu, v, o);
        vals[k] = v;
    }
    int lane = tid & 31, w = tid >> 5;
    if (lane == 0) {
        #pragma unroll
        for (int k = 0; k < 5; ++k) s_red[w * 5 + k] = vals[k];
    }
    __syncthreads();
    if (tid == 0) {
        #pragma unroll
        for (int k = 0; k < 5; ++k) {
            float s = 0.f;
            #pragma unroll
            for (int wq = 0; wq < 8; ++wq) s += s_red[wq * 5 + k];
            atomicAdd(&g_acc[k], (double)s);
        }
        __threadfence();
        unsigned ticket = atomicAdd(&g_count, 1u);
        if (ticket == gridDim.x - 1) {
            double a0 = atomicAdd(&g_acc[0], 0.0);
            double a1 = atomicAdd(&g_acc[1], 0.0);
            double a2 = atomicAdd(&g_acc[2], 0.0);
            double a3 = atomicAdd(&g_acc[3], 0.0);
            double a4 = atomicAdd(&g_acc[4], 0.0);
            float zwlT = (float)a0, zplT = (float)a1;
            float plT  = -(float)a2, olT = (float)a3, nobjT = (float)a4;
            float bsum = base_losses[0] + base_losses[1] + base_losses[2] + base_losses[3];
            int iv = *(const int*)step_ptr;
            float gs = (iv >= 0 && iv < 1000000000) ? (float)iv : *(const float*)step_ptr;
            float scaling = fminf(1.f, gs / 300000.f);
            float loss = bsum + zwlT * 10.f + zplT + plT + olT * scaling * 10.f;
            float res[6] = {loss, zwlT, zplT, plT, olT, nobjT};
            for (int k = 0; k < 6 && k < out_size; ++k) out[k] = res[k];
            __threadfence();
            g_acc[0] = 0.0; g_acc[1] = 0.0; g_acc[2] = 0.0;
            g_acc[3] = 0.0; g_acc[4] = 0.0;
            g_count = 0u;
        }
    }
}

extern "C" void kernel_launch(void* const* d_in, const int* in_sizes, int n_in,
                              void* d_out, int out_size) {
    const float* z_what      = (const float*)d_in[0];
    const float* z_pres_prob = (const float*)d_in[1];
    const float* z_pres      = (const float*)d_in[2];
    const float* base_losses = (const float*)d_in[3];
    const void*  gstep       = d_in[4];

    const size_t SMEM = (size_t)2 * NN * PADH * sizeof(half)
                      + (size_t)(2 * NN + 40) * sizeof(float);   // ~43.2 KB
    losses_kernel<<<GRID, 256, SMEM>>>(z_what, z_pres_prob, z_pres,
                                       base_losses, gstep,
                                       (float*)d_out, out_size);
}

// round 12
// speedup vs baseline: 1.1866x; 1.1866x over previous
#include <cuda_runtime.h>
#include <cuda_fp16.h>

// Fixed problem shapes
#define TT 4
#define BB 512
#define GG 16
#define NN 256
#define DD 32
#define PADH 40                 // halves per smem row (80B): conflict-free .128 row access
#define NPAIR ((TT - 1) * BB)   // 1536
#define GRID  740               // 148 SMs x 5 CTAs: one resident wave
#define NEG_BIG_F (-1e30f)

__device__ double g_acc[5];        // zwl, zpl, pl(sum cos*w), ol, nobj
__device__ unsigned int g_count;   // zero-init; reset by last CTA each replay

__device__ __forceinline__ unsigned h2u(half2 h) { return *reinterpret_cast<unsigned*>(&h); }
__device__ __forceinline__ half2    u2h(unsigned u) { return *reinterpret_cast<half2*>(&u); }
__device__ __forceinline__ float    hsumf(half2 h) { float2 f = __half22float2(h); return f.x + f.y; }

__global__ __launch_bounds__(256, 5) void losses_kernel(
    const float* __restrict__ z_what,
    const float* __restrict__ z_pres_prob,
    const float* __restrict__ z_pres,
    const float* __restrict__ base_losses,
    const void*  __restrict__ step_ptr,
    float* __restrict__ out, int out_size)
{
    const int tid = threadIdx.x;
    const int n   = tid;               // one thread per grid cell
    const int i   = n >> 4, j = n & 15;

    extern __shared__ char smraw[];
    half*  buf0 = (half*)smraw;                     // [NN][PADH] fp16 slice buffer
    half*  buf1 = buf0 + NN * PADH;                 // [NN][PADH] fp16 slice buffer
    float* s_pb = (float*)(smraw + (size_t)2 * NN * PADH * sizeof(half));
    float* s_nb = s_pb + NN;                        // 1 / ||wb[m]||
    float* s_red = s_nb + NN;                       // 40 floats

    float acc0 = 0.f, acc1 = 0.f, acc2 = 0.f, acc3 = 0.f, acc4 = 0.f;

    half* A = buf0;   // wa / hm buffer (destroyed by pool1 each pair)
    half* B = buf1;   // wb buffer (survives the pair)

    const bool chain = ((2 * blockIdx.x) % 3 != 2);   // sub0->sub1 same-batch reuse
    bool prefetched = false;

    #pragma unroll 1
    for (int sub = 0; sub < 3; ++sub) {
        int p;
        if (sub < 2) {
            p = 2 * blockIdx.x + sub;
        } else {
            if (blockIdx.x >= NPAIR - 2 * GRID) break;    // 56 leftover pairs
            p = 2 * GRID + blockIdx.x;
        }
        const bool reuse = (sub == 1) && chain;
        const int bb = p / 3;          // batch index (b-major pair order)
        const int tt = p - bb * 3;     // t of the left slice

        const size_t slice = (size_t)NN * DD;
        const float4* ga4 = (const float4*)(z_what + ((size_t)tt * BB + bb) * slice);
        const float4* gb4 = (const float4*)((const float*)ga4 + (size_t)BB * slice);

        if (prefetched) {
            // new wb already staged into old hm buffer during previous objects phase
            half* tmp = A; A = B; B = tmp;     // A = intact old wb (wa data); B = prefetched wb
            prefetched = false;
        } else if (reuse) {
            // ---- reuse without prefetch (shouldn't happen, kept for safety) ----
            half* tmp = A; A = B; B = tmp;
            float zwl = 0.f;
            #pragma unroll
            for (int it = 0; it < 8; ++it) {
                int k4 = it * 256 + tid;
                float4 vb = gb4[k4];
                int nn = k4 >> 3;
                int d0 = (k4 & 7) * 4;
                uint2 va16 = *(const uint2*)(A + nn * PADH + d0);
                float2 f01 = __half22float2(u2h(va16.x));
                float2 f23 = __half22float2(u2h(va16.y));
                float dx = vb.x - f01.x, dy = vb.y - f01.y;
                float dz = vb.z - f23.x, dw = vb.w - f23.y;
                zwl += dx*dx + dy*dy + dz*dz + dw*dw;
                half2 b0 = __floats2half2_rn(vb.x, vb.y), b1 = __floats2half2_rn(vb.z, vb.w);
                *(uint2*)(B + nn * PADH + d0) = make_uint2(h2u(b0), h2u(b1));
            }
            acc0 += zwl;
        } else {
            // ---- fresh: coalesced load of both slices; zwl exact fp32 ----
            float zwl = 0.f;
            #pragma unroll
            for (int it = 0; it < 8; ++it) {
                int k4 = it * 256 + tid;
                float4 va = ga4[k4];
                float4 vb = gb4[k4];
                int nn = k4 >> 3;
                int d0 = (k4 & 7) * 4;
                float dx = vb.x - va.x, dy = vb.y - va.y, dz = vb.z - va.z, dw = vb.w - va.w;
                zwl += dx*dx + dy*dy + dz*dz + dw*dw;
                half2 a0 = __floats2half2_rn(va.x, va.y), a1 = __floats2half2_rn(va.z, va.w);
                half2 b0 = __floats2half2_rn(vb.x, vb.y), b1 = __floats2half2_rn(vb.z, vb.w);
                *(uint2*)(A + nn * PADH + d0) = make_uint2(h2u(a0), h2u(a1));
                *(uint2*)(B + nn * PADH + d0) = make_uint2(h2u(b0), h2u(b1));
            }
            acc0 += zwl;
        }
        const float pa_n = z_pres_prob[((size_t)tt * BB + bb) * NN + n];
        const float pb_n = z_pres_prob[((size_t)(tt + 1) * BB + bb) * NN + n];
        s_pb[n] = pb_n;

        // ---- z_pres loss (tt = 0,1 windows only) ----
        if (tt < TT - 2) {
            const float* zp = z_pres + ((size_t)tt * BB + bb) * NN + n;
            float p0 = zp[0];
            float p1 = zp[(size_t)BB * NN];
            float p2 = zp[2 * (size_t)BB * NN];
            float sim = 1.f - (p2 - p0) * (p2 - p0);
            float del = (p2 - p1) * (p2 - p1) + (p0 - p1) * (p0 - p1);
            acc1 += sim * del;
        }
        __syncthreads();

        // ---- own rows: pr2 regs; pn2/nb2/dotc with split accumulators ----
        half2 pr2[16];
        half2 pnA = __float2half2_rn(0.f), pnB = pnA;
        half2 nbA = pnA, nbB = pnA, dcA = pnA, dcB = pnA;
        {
            const uint4* ra = (const uint4*)(A + n * PADH);
            const uint4* rb = (const uint4*)(B + n * PADH);
            #pragma unroll
            for (int k = 0; k < 4; ++k) {
                uint4 qa = ra[k], qb = rb[k];
                half2 a0 = u2h(qa.x), a1 = u2h(qa.y), a2 = u2h(qa.z), a3 = u2h(qa.w);
                half2 b0 = u2h(qb.x), b1 = u2h(qb.y), b2 = u2h(qb.z), b3 = u2h(qb.w);
                pr2[4*k+0] = a0; pr2[4*k+1] = a1; pr2[4*k+2] = a2; pr2[4*k+3] = a3;
                pnA = __hfma2(a0, a0, pnA); pnB = __hfma2(a1, a1, pnB);
                pnA = __hfma2(a2, a2, pnA); pnB = __hfma2(a3, a3, pnB);
                nbA = __hfma2(b0, b0, nbA); nbB = __hfma2(b1, b1, nbB);
                nbA = __hfma2(b2, b2, nbA); nbB = __hfma2(b3, b3, nbB);
                dcA = __hfma2(a0, b0, dcA); dcB = __hfma2(a1, b1, dcB);
                dcA = __hfma2(a2, b2, dcA); dcB = __hfma2(a3, b3, dcB);
            }
        }
        const float nbn     = sqrtf(hsumf(__hadd2(nbA, nbB)));
        const float prior_n = sqrtf(hsumf(__hadd2(pnA, pnB)));
        const float dotc    = hsumf(__hadd2(dcA, dcB));
        const float rnb = __fdividef(1.f, fmaxf(nbn, 1e-20f));
        s_nb[n] = rnb;

        // ---- pool pass 1: horizontal 3-max of |pr|*pa, own-row overwrite (safe) ----
        {
            const half2 pa2 = __float2half2_rn(pa_n);
            const bool lok = (j > 0), rok = (j < 15);
            uint4* rowh = (uint4*)(A + n * PADH);
            #pragma unroll
            for (int k4o = 0; k4o < 4; ++k4o) {
                unsigned hv[4];
                #pragma unroll
                for (int c = 0; c < 4; ++c) {
                    half2 wv = __hmul2(__habs2(pr2[4 * k4o + c]), pa2);
                    unsigned w = h2u(wv);
                    unsigned l = __shfl_up_sync(0xffffffffu, w, 1);
                    unsigned r = __shfl_down_sync(0xffffffffu, w, 1);
                    half2 hm = wv;
                    if (lok) hm = __hmax2(hm, u2h(l));
                    if (rok) hm = __hmax2(hm, u2h(r));
                    hv[c] = h2u(hm);
                }
                rowh[k4o] = make_uint4(hv[0], hv[1], hv[2], hv[3]);
            }
        }
        __syncthreads();

        // ---- pool pass 2: vertical 3-max + cosine (split accumulators) ----
        half2 dpA = __float2half2_rn(0.f), dpB = dpA, naA = dpA, naB = dpA;
        {
            const uint4* r0 = (const uint4*)(A + n * PADH);
            const uint4* ru = (i > 0)  ? (const uint4*)(A + (n - 16) * PADH) : r0;
            const uint4* rd = (i < 15) ? (const uint4*)(A + (n + 16) * PADH) : r0;
            const uint4* rb = (const uint4*)(B + n * PADH);
            #pragma unroll
            for (int k = 0; k < 4; ++k) {
                uint4 q0 = r0[k], qu = ru[k], qd = rd[k], qb = rb[k];
                half2 m0 = __hmax2(u2h(q0.x), __hmax2(u2h(qu.x), u2h(qd.x)));
                half2 m1 = __hmax2(u2h(q0.y), __hmax2(u2h(qu.y), u2h(qd.y)));
                half2 m2 = __hmax2(u2h(q0.z), __hmax2(u2h(qu.z), u2h(qd.z)));
                half2 m3 = __hmax2(u2h(q0.w), __hmax2(u2h(qu.w), u2h(qd.w)));
                dpA = __hfma2(m0, __habs2(u2h(qb.x)), dpA);
                dpB = __hfma2(m1, __habs2(u2h(qb.y)), dpB);
                dpA = __hfma2(m2, __habs2(u2h(qb.z)), dpA);
                dpB = __hfma2(m3, __habs2(u2h(qb.w)), dpB);
                naA = __hfma2(m0, m0, naA); naB = __hfma2(m1, m1, naB);
                naA = __hfma2(m2, m2, naA); naB = __hfma2(m3, m3, naB);
            }
        }
        {
            float dotp = hsumf(__hadd2(dpA, dpB));
            float na2  = hsumf(__hadd2(naA, naB));
            float cosim = __fdividef(dotp * pb_n, fmaxf(sqrtf(na2) * (pb_n * nbn), 1e-6f));
            acc2 += cosim * 0.5f * (pa_n + pb_n);  // pool_loss = -sum
        }
        __syncthreads();   // hm buffer consumed; safe for prefetch to overwrite it

        // ---- objects phase + (optionally) prefetch next pair's wb into hm buffer ----
        const bool do_prefetch = (sub == 0) && chain;
        if (do_prefetch) {
            // next pair (p+1, same batch): its wb slice is t = tt+2
            const float4* gbn = (const float4*)(z_what + ((size_t)(tt + 2) * BB + bb) * slice);
            float zwlp = 0.f;
            #pragma unroll
            for (int it = 0; it < 8; ++it) {
                int k4 = it * 256 + tid;
                float4 vb = gbn[k4];
                int nn = k4 >> 3;
                int d0 = (k4 & 7) * 4;
                uint2 va16 = *(const uint2*)(B + nn * PADH + d0);   // old wb = next wa (fp16)
                float2 f01 = __half22float2(u2h(va16.x));
                float2 f23 = __half22float2(u2h(va16.y));
                float dx = vb.x - f01.x, dy = vb.y - f01.y;
                float dz = vb.z - f23.x, dw = vb.w - f23.y;
                zwlp += dx*dx + dy*dy + dz*dz + dw*dw;
                half2 b0 = __floats2half2_rn(vb.x, vb.y), b1 = __floats2half2_rn(vb.z, vb.w);
                *(uint2*)(A + nn * PADH + d0) = make_uint2(h2u(b0), h2u(b1));
            }
            acc0 += zwlp;
            prefetched = true;
        }

        // ---- objects: 8 branchless neighbor dots, 4-way trees, no divisions ----
        const float rp = __fdividef(1.f, fmaxf(prior_n, 1e-20f));
        float sumd, maxd;
        bool anyp;
        {
            bool pc = pb_n > 0.5f;
            float vc = dotc * rp * rnb;
            sumd = pc ? vc : 0.f;
            maxd = pc ? vc : NEG_BIG_F;
            anyp = pc;
        }
        const int DI[8] = {-1,-1,-1, 0, 0, 1, 1, 1};
        const int DJ[8] = {-1, 0, 1,-1, 1,-1, 0, 1};
        #pragma unroll
        for (int q = 0; q < 8; ++q) {
            const int m = (((i + DI[q]) & 15) << 4) | ((j + DJ[q]) & 15);
            const float pbm = s_pb[m];
            const float rnm = s_nb[m];
            const uint4* rn4 = (const uint4*)(B + m * PADH);
            uint4 q0 = rn4[0], q1 = rn4[1], q2 = rn4[2], q3 = rn4[3];
            half2 d0 = __hmul2(pr2[0],  u2h(q0.x));
            half2 d1 = __hmul2(pr2[1],  u2h(q0.y));
            half2 d2 = __hmul2(pr2[2],  u2h(q0.z));
            half2 d3 = __hmul2(pr2[3],  u2h(q0.w));
            d0 = __hfma2(pr2[4],  u2h(q1.x), d0);
            d1 = __hfma2(pr2[5],  u2h(q1.y), d1);
            d2 = __hfma2(pr2[6],  u2h(q1.z), d2);
            d3 = __hfma2(pr2[7],  u2h(q1.w), d3);
            d0 = __hfma2(pr2[8],  u2h(q2.x), d0);
            d1 = __hfma2(pr2[9],  u2h(q2.y), d1);
            d2 = __hfma2(pr2[10], u2h(q2.z), d2);
            d3 = __hfma2(pr2[11], u2h(q2.w), d3);
            d0 = __hfma2(pr2[12], u2h(q3.x), d0);
            d1 = __hfma2(pr2[13], u2h(q3.y), d1);
            d2 = __hfma2(pr2[14], u2h(q3.z), d2);
            d3 = __hfma2(pr2[15], u2h(q3.w), d3);
            half2 ds = __hadd2(__hadd2(d0, d1), __hadd2(d2, d3));
            float v = hsumf(ds) * rp * rnm;
            bool pq = pbm > 0.5f;
            sumd += pq ? v : 0.f;
            maxd = fmaxf(maxd, pq ? v : NEG_BIG_F);
            anyp |= pq;
        }
        {
            bool detected = pa_n > 0.5f;
            if (detected && anyp) acc3 += sumd - 5.f * maxd;
            if (detected) acc4 += 1.f;
        }

        __syncthreads();   // protect smem before next iteration
    }

    // ---- one block reduction per CTA + global accumulate ----
    float vals[5] = {acc0, acc1, acc2, acc3, acc4};
    #pragma unroll
    for (int k = 0; k < 5; ++k) {
        float v = vals[k];
        #pragma unroll
        for (int o = 16; o > 0; o >>= 1) v += __shfl_down_sync(0xffffffffu, v, o);
        vals[k] = v;
    }
    int lane = tid & 31, w = tid >> 5;
    if (lane == 0) {
        #pragma unroll
        for (int k = 0; k < 5; ++k) s_red[w * 5 + k] = vals[k];
    }
    __syncthreads();
    if (tid == 0) {
        #pragma unroll
        for (int k = 0; k < 5; ++k) {
            float s = 0.f;
            #pragma unroll
            for (int wq = 0; wq < 8; ++wq) s += s_red[wq * 5 + k];
            atomicAdd(&g_acc[k], (double)s);
        }
        __threadfence();
        unsigned ticket = atomicAdd(&g_count, 1u);
        if (ticket == gridDim.x - 1) {
            double a0 = atomicAdd(&g_acc[0], 0.0);
            double a1 = atomicAdd(&g_acc[1], 0.0);
            double a2 = atomicAdd(&g_acc[2], 0.0);
            double a3 = atomicAdd(&g_acc[3], 0.0);
            double a4 = atomicAdd(&g_acc[4], 0.0);
            float zwlT = (float)a0, zplT = (float)a1;
            float plT  = -(float)a2, olT = (float)a3, nobjT = (float)a4;
            float bsum = base_losses[0] + base_losses[1] + base_losses[2] + base_losses[3];
            int iv = *(const int*)step_ptr;
            float gs = (iv >= 0 && iv < 1000000000) ? (float)iv : *(const float*)step_ptr;
            float scaling = fminf(1.f, gs / 300000.f);
            float loss = bsum + zwlT * 10.f + zplT + plT + olT * scaling * 10.f;
            float res[6] = {loss, zwlT, zplT, plT, olT, nobjT};
            for (int k = 0; k < 6 && k < out_size; ++k) out[k] = res[k];
            __threadfence();
            g_acc[0] = 0.0; g_acc[1] = 0.0; g_acc[2] = 0.0;
            g_acc[3] = 0.0; g_acc[4] = 0.0;
            g_count = 0u;
        }
    }
}

extern "C" void kernel_launch(void* const* d_in, const int* in_sizes, int n_in,
                              void* d_out, int out_size) {
    const float* z_what      = (const float*)d_in[0];
    const float* z_pres_prob = (const float*)d_in[1];
    const float* z_pres      = (const float*)d_in[2];
    const float* base_losses = (const float*)d_in[3];
    const void*  gstep       = d_in[4];

    const size_t SMEM = (size_t)2 * NN * PADH * sizeof(half)
                      + (size_t)(2 * NN + 40) * sizeof(float);   // ~43.2 KB
    losses_kernel<<<GRID, 256, SMEM>>>(z_what, z_pres_prob, z_pres,
                                       base_losses, gstep,
                                       (float*)d_out, out_size);
}